// round 1
// baseline (speedup 1.0000x reference)
#include <cuda_runtime.h>
#include <cuda_bf16.h>
#include <math.h>

// Problem constants
#define BATCH 2
#define SEQ   2048
#define NTOK  4096          // BATCH*SEQ
#define EMB   1024
#define HEADS 16
#define HDIM  64
#define FFDIM 4096

// ---------------------------------------------------------------------------
// Scratch buffers (device globals; no allocation allowed)
// ---------------------------------------------------------------------------
__device__ float d_buf_h   [(size_t)NTOK * EMB];        // LN output (reused)
__device__ float d_buf_qkv [(size_t)NTOK * 3 * EMB];    // QKV projection
__device__ float d_buf_attn[(size_t)NTOK * EMB];        // attention output
__device__ float d_buf_x1  [(size_t)NTOK * EMB];        // x after first residual
__device__ float d_buf_ff1 [(size_t)NTOK * FFDIM];      // FF1 + GELU output

// ---------------------------------------------------------------------------
// LayerNorm: one block per row of 1024
// ---------------------------------------------------------------------------
__global__ __launch_bounds__(256)
void ln_kernel(const float* __restrict__ x, const float* __restrict__ gamma,
               const float* __restrict__ beta, float* __restrict__ y)
{
    const int row = blockIdx.x;
    const int t = threadIdx.x;
    const float4 v = ((const float4*)(x + (size_t)row * EMB))[t];
    __shared__ float sh[8];

    float s = v.x + v.y + v.z + v.w;
    #pragma unroll
    for (int o = 16; o; o >>= 1) s += __shfl_xor_sync(0xffffffffu, s, o);
    if ((t & 31) == 0) sh[t >> 5] = s;
    __syncthreads();
    float tot = 0.f;
    #pragma unroll
    for (int w = 0; w < 8; ++w) tot += sh[w];
    const float mu = tot * (1.0f / (float)EMB);

    const float dx0 = v.x - mu, dx1 = v.y - mu, dx2 = v.z - mu, dx3 = v.w - mu;
    float q = dx0*dx0 + dx1*dx1 + dx2*dx2 + dx3*dx3;
    __syncthreads();
    #pragma unroll
    for (int o = 16; o; o >>= 1) q += __shfl_xor_sync(0xffffffffu, q, o);
    if ((t & 31) == 0) sh[t >> 5] = q;
    __syncthreads();
    float tq = 0.f;
    #pragma unroll
    for (int w = 0; w < 8; ++w) tq += sh[w];
    const float rstd = rsqrtf(tq * (1.0f / (float)EMB) + 1e-5f);

    const float4 g4 = ((const float4*)gamma)[t];
    const float4 b4 = ((const float4*)beta)[t];
    float4 o4;
    o4.x = dx0 * rstd * g4.x + b4.x;
    o4.y = dx1 * rstd * g4.y + b4.y;
    o4.z = dx2 * rstd * g4.z + b4.z;
    o4.w = dx3 * rstd * g4.w + b4.w;
    ((float4*)(y + (size_t)row * EMB))[t] = o4;
}

// ---------------------------------------------------------------------------
// SGEMM: C[M,N] = A[M,K] @ W[N,K]^T + bias  (+ epilogue)
// mode 0: bias only ; mode 1: bias + exact GELU ; mode 2: bias + residual
// 128x128 tile, BK=16, 256 threads, 8x8 per thread (2x2 of 4x4 float4 frags)
// ---------------------------------------------------------------------------
__device__ __forceinline__ float gelu_exact(float v)
{
    return 0.5f * v * (1.0f + erff(v * 0.70710678118654752f));
}

__global__ __launch_bounds__(256, 2)
void sgemm_kernel(const float* __restrict__ A, const float* __restrict__ W,
                  const float* __restrict__ bias, const float* __restrict__ res,
                  float* __restrict__ C, int M, int N, int K, int mode)
{
    __shared__ __align__(16) float As[16][132];
    __shared__ __align__(16) float Bs[16][132];

    const int tid = threadIdx.x;
    const int tx = tid & 15;
    const int ty = tid >> 4;
    const int row0 = blockIdx.y << 7;
    const int col0 = blockIdx.x << 7;

    const int lr = tid >> 2;         // 0..63 (tile row for loads)
    const int lc = (tid & 3) << 2;   // 0,4,8,12 (k-col for loads)

    float acc[2][2][4][4];
    #pragma unroll
    for (int a = 0; a < 2; ++a)
        #pragma unroll
        for (int b = 0; b < 2; ++b)
            #pragma unroll
            for (int i = 0; i < 4; ++i)
                #pragma unroll
                for (int j = 0; j < 4; ++j) acc[a][b][i][j] = 0.f;

    const float* Ap = A + (size_t)(row0 + lr) * K + lc;
    const float* Wp = W + (size_t)(col0 + lr) * K + lc;
    const size_t off64 = (size_t)64 * K;

    for (int k0 = 0; k0 < K; k0 += 16) {
        const float4 a0 = *(const float4*)(Ap + k0);
        const float4 a1 = *(const float4*)(Ap + k0 + off64);
        const float4 b0 = *(const float4*)(Wp + k0);
        const float4 b1 = *(const float4*)(Wp + k0 + off64);
        __syncthreads();
        As[lc + 0][lr] = a0.x; As[lc + 1][lr] = a0.y;
        As[lc + 2][lr] = a0.z; As[lc + 3][lr] = a0.w;
        As[lc + 0][lr + 64] = a1.x; As[lc + 1][lr + 64] = a1.y;
        As[lc + 2][lr + 64] = a1.z; As[lc + 3][lr + 64] = a1.w;
        Bs[lc + 0][lr] = b0.x; Bs[lc + 1][lr] = b0.y;
        Bs[lc + 2][lr] = b0.z; Bs[lc + 3][lr] = b0.w;
        Bs[lc + 0][lr + 64] = b1.x; Bs[lc + 1][lr + 64] = b1.y;
        Bs[lc + 2][lr + 64] = b1.z; Bs[lc + 3][lr + 64] = b1.w;
        __syncthreads();

        #pragma unroll
        for (int k = 0; k < 16; ++k) {
            const float4 fa0 = *(const float4*)&As[k][ty << 2];
            const float4 fa1 = *(const float4*)&As[k][(ty << 2) + 64];
            const float4 fb0 = *(const float4*)&Bs[k][tx << 2];
            const float4 fb1 = *(const float4*)&Bs[k][(tx << 2) + 64];
            const float fa[2][4] = {{fa0.x, fa0.y, fa0.z, fa0.w},
                                    {fa1.x, fa1.y, fa1.z, fa1.w}};
            const float fb[2][4] = {{fb0.x, fb0.y, fb0.z, fb0.w},
                                    {fb1.x, fb1.y, fb1.z, fb1.w}};
            #pragma unroll
            for (int a = 0; a < 2; ++a)
                #pragma unroll
                for (int b = 0; b < 2; ++b)
                    #pragma unroll
                    for (int i = 0; i < 4; ++i)
                        #pragma unroll
                        for (int j = 0; j < 4; ++j)
                            acc[a][b][i][j] = fmaf(fa[a][i], fb[b][j], acc[a][b][i][j]);
        }
    }

    #pragma unroll
    for (int a = 0; a < 2; ++a)
        #pragma unroll
        for (int i = 0; i < 4; ++i) {
            const int r = row0 + a * 64 + (ty << 2) + i;
            #pragma unroll
            for (int b = 0; b < 2; ++b) {
                const int c = col0 + b * 64 + (tx << 2);
                float4 o;
                o.x = acc[a][b][i][0] + bias[c + 0];
                o.y = acc[a][b][i][1] + bias[c + 1];
                o.z = acc[a][b][i][2] + bias[c + 2];
                o.w = acc[a][b][i][3] + bias[c + 3];
                if (mode == 1) {
                    o.x = gelu_exact(o.x); o.y = gelu_exact(o.y);
                    o.z = gelu_exact(o.z); o.w = gelu_exact(o.w);
                } else if (mode == 2) {
                    const float4 rv = *(const float4*)(res + (size_t)r * N + c);
                    o.x += rv.x; o.y += rv.y; o.z += rv.z; o.w += rv.w;
                }
                *(float4*)(C + (size_t)r * N + c) = o;
            }
        }
}

// ---------------------------------------------------------------------------
// Flash-style attention (fp32, online softmax).
// grid: (SEQ/64, BATCH*HEADS), block 256.
// 64-query tile x 64-key tiles, D=64. Per thread: 4 query rows x 4 (key|dim)
// lanes, interleaved (L + 16*j) for conflict-free smem (stride 65).
// ---------------------------------------------------------------------------
#define SSTR 65
#define ATTN_SMEM (4 * 64 * SSTR * 4)

__global__ __launch_bounds__(256)
void attn_kernel(const float* __restrict__ qkv, float* __restrict__ out)
{
    extern __shared__ float sm[];
    float* Qs = sm;
    float* Ks = sm + 64 * SSTR;
    float* Vs = sm + 2 * 64 * SSTR;
    float* Ps = sm + 3 * 64 * SSTR;

    const int tid = threadIdx.x;
    const int L  = tid & 15;
    const int gq = tid >> 4;          // 16 groups; rows gq*4 .. gq*4+3
    const int qt = blockIdx.x;
    const int b  = blockIdx.y >> 4;
    const int h  = blockIdx.y & 15;

    const int lrow = tid >> 2;        // 0..63
    const int lcol = (tid & 3) << 4;  // 0,16,32,48

    // Load Q tile (64 x 64)
    {
        const float* qb = qkv + ((size_t)(b * SEQ + qt * 64 + lrow)) * (3 * EMB)
                              + h * HDIM + lcol;
        #pragma unroll
        for (int i = 0; i < 4; ++i) {
            const float4 v = *(const float4*)(qb + i * 4);
            const int c = lcol + i * 4;
            Qs[lrow * SSTR + c + 0] = v.x;
            Qs[lrow * SSTR + c + 1] = v.y;
            Qs[lrow * SSTR + c + 2] = v.z;
            Qs[lrow * SSTR + c + 3] = v.w;
        }
    }

    float m_r[4], l_r[4], acc[4][4];
    #pragma unroll
    for (int i = 0; i < 4; ++i) {
        m_r[i] = -1e30f; l_r[i] = 0.f;
        #pragma unroll
        for (int j = 0; j < 4; ++j) acc[i][j] = 0.f;
    }

    const float* kb = qkv + ((size_t)(b * SEQ + lrow)) * (3 * EMB)
                          + EMB + h * HDIM + lcol;
    const float* vb = kb + EMB;

    for (int kt = 0; kt < SEQ / 64; ++kt) {
        const float* kp = kb + (size_t)kt * 64 * (3 * EMB);
        const float* vp = vb + (size_t)kt * 64 * (3 * EMB);
        #pragma unroll
        for (int i = 0; i < 4; ++i) {
            const float4 kv4 = *(const float4*)(kp + i * 4);
            const float4 vv4 = *(const float4*)(vp + i * 4);
            const int c = lcol + i * 4;
            Ks[lrow * SSTR + c + 0] = kv4.x; Ks[lrow * SSTR + c + 1] = kv4.y;
            Ks[lrow * SSTR + c + 2] = kv4.z; Ks[lrow * SSTR + c + 3] = kv4.w;
            Vs[lrow * SSTR + c + 0] = vv4.x; Vs[lrow * SSTR + c + 1] = vv4.y;
            Vs[lrow * SSTR + c + 2] = vv4.z; Vs[lrow * SSTR + c + 3] = vv4.w;
        }
        __syncthreads();

        // scores: s[i][j] = Q[gq*4+i] . K[L+16*j]
        float s[4][4];
        #pragma unroll
        for (int i = 0; i < 4; ++i)
            #pragma unroll
            for (int j = 0; j < 4; ++j) s[i][j] = 0.f;

        #pragma unroll 8
        for (int kd = 0; kd < 64; ++kd) {
            float rq[4];
            #pragma unroll
            for (int i = 0; i < 4; ++i) rq[i] = Qs[(gq * 4 + i) * SSTR + kd];
            #pragma unroll
            for (int j = 0; j < 4; ++j) {
                const float kk = Ks[(L + 16 * j) * SSTR + kd];
                #pragma unroll
                for (int i = 0; i < 4; ++i) s[i][j] = fmaf(rq[i], kk, s[i][j]);
            }
        }

        // online softmax update (per query row; stats replicated over 16 lanes)
        #pragma unroll
        for (int i = 0; i < 4; ++i) {
            float tm = -1e30f;
            #pragma unroll
            for (int j = 0; j < 4; ++j) { s[i][j] *= 0.125f; tm = fmaxf(tm, s[i][j]); }
            #pragma unroll
            for (int o = 8; o; o >>= 1) tm = fmaxf(tm, __shfl_xor_sync(0xffffffffu, tm, o));
            const float mnew = fmaxf(m_r[i], tm);
            const float alpha = __expf(m_r[i] - mnew);
            float psum = 0.f;
            #pragma unroll
            for (int j = 0; j < 4; ++j) {
                const float p = __expf(s[i][j] - mnew);
                s[i][j] = p; psum += p;
            }
            #pragma unroll
            for (int o = 8; o; o >>= 1) psum += __shfl_xor_sync(0xffffffffu, psum, o);
            l_r[i] = l_r[i] * alpha + psum;
            m_r[i] = mnew;
            #pragma unroll
            for (int j = 0; j < 4; ++j) acc[i][j] *= alpha;
            #pragma unroll
            for (int j = 0; j < 4; ++j) Ps[(gq * 4 + i) * SSTR + L + 16 * j] = s[i][j];
        }
        __syncthreads();

        // O += P @ V
        #pragma unroll 8
        for (int k = 0; k < 64; ++k) {
            float vv[4];
            #pragma unroll
            for (int j = 0; j < 4; ++j) vv[j] = Vs[k * SSTR + L + 16 * j];
            #pragma unroll
            for (int i = 0; i < 4; ++i) {
                const float p = Ps[(gq * 4 + i) * SSTR + k];
                #pragma unroll
                for (int j = 0; j < 4; ++j) acc[i][j] = fmaf(p, vv[j], acc[i][j]);
            }
        }
        __syncthreads();
    }

    // normalize + write: out[(b,q), h*64 + (L+16j)]
    #pragma unroll
    for (int i = 0; i < 4; ++i) {
        const float inv = 1.0f / l_r[i];
        const int r = b * SEQ + qt * 64 + gq * 4 + i;
        #pragma unroll
        for (int j = 0; j < 4; ++j)
            out[(size_t)r * EMB + h * HDIM + L + 16 * j] = acc[i][j] * inv;
    }
}

// ---------------------------------------------------------------------------
// Launch
// ---------------------------------------------------------------------------
extern "C" void kernel_launch(void* const* d_in, const int* in_sizes, int n_in,
                              void* d_out, int out_size)
{
    (void)in_sizes; (void)n_in; (void)out_size;
    const float* x     = (const float*)d_in[0];
    const float* qkv_w = (const float*)d_in[1];
    const float* qkv_b = (const float*)d_in[2];
    const float* out_w = (const float*)d_in[3];
    const float* out_b = (const float*)d_in[4];
    const float* ff1_w = (const float*)d_in[5];
    const float* ff1_b = (const float*)d_in[6];
    const float* ff2_w = (const float*)d_in[7];
    const float* ff2_b = (const float*)d_in[8];
    const float* ln1_g = (const float*)d_in[9];
    const float* ln1_b = (const float*)d_in[10];
    const float* ln2_g = (const float*)d_in[11];
    const float* ln2_b = (const float*)d_in[12];
    float* out = (float*)d_out;

    float *bh, *bqkv, *battn, *bx1, *bff1;
    cudaGetSymbolAddress((void**)&bh,    d_buf_h);
    cudaGetSymbolAddress((void**)&bqkv,  d_buf_qkv);
    cudaGetSymbolAddress((void**)&battn, d_buf_attn);
    cudaGetSymbolAddress((void**)&bx1,   d_buf_x1);
    cudaGetSymbolAddress((void**)&bff1,  d_buf_ff1);

    cudaFuncSetAttribute(attn_kernel,
                         cudaFuncAttributeMaxDynamicSharedMemorySize, ATTN_SMEM);

    // 1. LN1
    ln_kernel<<<NTOK, 256>>>(x, ln1_g, ln1_b, bh);
    // 2. QKV projection: [4096,1024] @ [3072,1024]^T
    sgemm_kernel<<<dim3(3 * EMB / 128, NTOK / 128), 256>>>(
        bh, qkv_w, qkv_b, nullptr, bqkv, NTOK, 3 * EMB, EMB, 0);
    // 3. Attention
    attn_kernel<<<dim3(SEQ / 64, BATCH * HEADS), 256, ATTN_SMEM>>>(bqkv, battn);
    // 4. Output projection + residual(x)
    sgemm_kernel<<<dim3(EMB / 128, NTOK / 128), 256>>>(
        battn, out_w, out_b, x, bx1, NTOK, EMB, EMB, 2);
    // 5. LN2
    ln_kernel<<<NTOK, 256>>>(bx1, ln2_g, ln2_b, bh);
    // 6. FF1 + GELU: [4096,1024] @ [4096,1024]^T
    sgemm_kernel<<<dim3(FFDIM / 128, NTOK / 128), 256>>>(
        bh, ff1_w, ff1_b, nullptr, bff1, NTOK, FFDIM, EMB, 1);
    // 7. FF2 + residual(x1) -> d_out
    sgemm_kernel<<<dim3(EMB / 128, NTOK / 128), 256>>>(
        bff1, ff2_w, ff2_b, bx1, out, NTOK, EMB, FFDIM, 2);
}

// round 2
// speedup vs baseline: 1.0009x; 1.0009x over previous
#include <cuda_runtime.h>
#include <cuda_bf16.h>
#include <math.h>

// Problem constants
#define BATCH 2
#define SEQ   2048
#define NTOK  4096          // BATCH*SEQ
#define EMB   1024
#define HEADS 16
#define HDIM  64
#define FFDIM 4096

// ---------------------------------------------------------------------------
// Scratch buffers (device globals; no allocation allowed)
// ---------------------------------------------------------------------------
__device__ float d_buf_h   [(size_t)NTOK * EMB];        // LN output (reused)
__device__ float d_buf_qkv [(size_t)NTOK * 3 * EMB];    // QKV projection
__device__ float d_buf_attn[(size_t)NTOK * EMB];        // attention output
__device__ float d_buf_x1  [(size_t)NTOK * EMB];        // x after first residual
__device__ float d_buf_ff1 [(size_t)NTOK * FFDIM];      // FF1 + GELU output

// ---------------------------------------------------------------------------
// LayerNorm: one block per row of 1024
// ---------------------------------------------------------------------------
__global__ __launch_bounds__(256)
void ln_kernel(const float* __restrict__ x, const float* __restrict__ gamma,
               const float* __restrict__ beta, float* __restrict__ y)
{
    const int row = blockIdx.x;
    const int t = threadIdx.x;
    const float4 v = ((const float4*)(x + (size_t)row * EMB))[t];
    __shared__ float sh[8];

    float s = v.x + v.y + v.z + v.w;
    #pragma unroll
    for (int o = 16; o; o >>= 1) s += __shfl_xor_sync(0xffffffffu, s, o);
    if ((t & 31) == 0) sh[t >> 5] = s;
    __syncthreads();
    float tot = 0.f;
    #pragma unroll
    for (int w = 0; w < 8; ++w) tot += sh[w];
    const float mu = tot * (1.0f / (float)EMB);

    const float dx0 = v.x - mu, dx1 = v.y - mu, dx2 = v.z - mu, dx3 = v.w - mu;
    float q = dx0*dx0 + dx1*dx1 + dx2*dx2 + dx3*dx3;
    __syncthreads();
    #pragma unroll
    for (int o = 16; o; o >>= 1) q += __shfl_xor_sync(0xffffffffu, q, o);
    if ((t & 31) == 0) sh[t >> 5] = q;
    __syncthreads();
    float tq = 0.f;
    #pragma unroll
    for (int w = 0; w < 8; ++w) tq += sh[w];
    const float rstd = rsqrtf(tq * (1.0f / (float)EMB) + 1e-5f);

    const float4 g4 = ((const float4*)gamma)[t];
    const float4 b4 = ((const float4*)beta)[t];
    float4 o4;
    o4.x = dx0 * rstd * g4.x + b4.x;
    o4.y = dx1 * rstd * g4.y + b4.y;
    o4.z = dx2 * rstd * g4.z + b4.z;
    o4.w = dx3 * rstd * g4.w + b4.w;
    ((float4*)(y + (size_t)row * EMB))[t] = o4;
}

// ---------------------------------------------------------------------------
// SGEMM: C[M,N] = A[M,K] @ W[N,K]^T + bias  (+ epilogue)
// mode 0: bias only ; mode 1: bias + exact GELU ; mode 2: bias + residual
// 128x128 tile, BK=16, 256 threads, 8x8 per thread (2x2 of 4x4 float4 frags)
// ---------------------------------------------------------------------------
__device__ __forceinline__ float gelu_exact(float v)
{
    return 0.5f * v * (1.0f + erff(v * 0.70710678118654752f));
}

__global__ __launch_bounds__(256, 2)
void sgemm_kernel(const float* __restrict__ A, const float* __restrict__ W,
                  const float* __restrict__ bias, const float* __restrict__ res,
                  float* __restrict__ C, int M, int N, int K, int mode)
{
    __shared__ __align__(16) float As[16][132];
    __shared__ __align__(16) float Bs[16][132];

    const int tid = threadIdx.x;
    const int tx = tid & 15;
    const int ty = tid >> 4;
    const int row0 = blockIdx.y << 7;
    const int col0 = blockIdx.x << 7;

    const int lr = tid >> 2;         // 0..63 (tile row for loads)
    const int lc = (tid & 3) << 2;   // 0,4,8,12 (k-col for loads)

    float acc[2][2][4][4];
    #pragma unroll
    for (int a = 0; a < 2; ++a)
        #pragma unroll
        for (int b = 0; b < 2; ++b)
            #pragma unroll
            for (int i = 0; i < 4; ++i)
                #pragma unroll
                for (int j = 0; j < 4; ++j) acc[a][b][i][j] = 0.f;

    const float* Ap = A + (size_t)(row0 + lr) * K + lc;
    const float* Wp = W + (size_t)(col0 + lr) * K + lc;
    const size_t off64 = (size_t)64 * K;

    for (int k0 = 0; k0 < K; k0 += 16) {
        const float4 a0 = *(const float4*)(Ap + k0);
        const float4 a1 = *(const float4*)(Ap + k0 + off64);
        const float4 b0 = *(const float4*)(Wp + k0);
        const float4 b1 = *(const float4*)(Wp + k0 + off64);
        __syncthreads();
        As[lc + 0][lr] = a0.x; As[lc + 1][lr] = a0.y;
        As[lc + 2][lr] = a0.z; As[lc + 3][lr] = a0.w;
        As[lc + 0][lr + 64] = a1.x; As[lc + 1][lr + 64] = a1.y;
        As[lc + 2][lr + 64] = a1.z; As[lc + 3][lr + 64] = a1.w;
        Bs[lc + 0][lr] = b0.x; Bs[lc + 1][lr] = b0.y;
        Bs[lc + 2][lr] = b0.z; Bs[lc + 3][lr] = b0.w;
        Bs[lc + 0][lr + 64] = b1.x; Bs[lc + 1][lr + 64] = b1.y;
        Bs[lc + 2][lr + 64] = b1.z; Bs[lc + 3][lr + 64] = b1.w;
        __syncthreads();

        #pragma unroll
        for (int k = 0; k < 16; ++k) {
            const float4 fa0 = *(const float4*)&As[k][ty << 2];
            const float4 fa1 = *(const float4*)&As[k][(ty << 2) + 64];
            const float4 fb0 = *(const float4*)&Bs[k][tx << 2];
            const float4 fb1 = *(const float4*)&Bs[k][(tx << 2) + 64];
            const float fa[2][4] = {{fa0.x, fa0.y, fa0.z, fa0.w},
                                    {fa1.x, fa1.y, fa1.z, fa1.w}};
            const float fb[2][4] = {{fb0.x, fb0.y, fb0.z, fb0.w},
                                    {fb1.x, fb1.y, fb1.z, fb1.w}};
            #pragma unroll
            for (int a = 0; a < 2; ++a)
                #pragma unroll
                for (int b = 0; b < 2; ++b)
                    #pragma unroll
                    for (int i = 0; i < 4; ++i)
                        #pragma unroll
                        for (int j = 0; j < 4; ++j)
                            acc[a][b][i][j] = fmaf(fa[a][i], fb[b][j], acc[a][b][i][j]);
        }
    }

    #pragma unroll
    for (int a = 0; a < 2; ++a)
        #pragma unroll
        for (int i = 0; i < 4; ++i) {
            const int r = row0 + a * 64 + (ty << 2) + i;
            #pragma unroll
            for (int b = 0; b < 2; ++b) {
                const int c = col0 + b * 64 + (tx << 2);
                float4 o;
                o.x = acc[a][b][i][0] + bias[c + 0];
                o.y = acc[a][b][i][1] + bias[c + 1];
                o.z = acc[a][b][i][2] + bias[c + 2];
                o.w = acc[a][b][i][3] + bias[c + 3];
                if (mode == 1) {
                    o.x = gelu_exact(o.x); o.y = gelu_exact(o.y);
                    o.z = gelu_exact(o.z); o.w = gelu_exact(o.w);
                } else if (mode == 2) {
                    const float4 rv = *(const float4*)(res + (size_t)r * N + c);
                    o.x += rv.x; o.y += rv.y; o.z += rv.z; o.w += rv.w;
                }
                *(float4*)(C + (size_t)r * N + c) = o;
            }
        }
}

// ---------------------------------------------------------------------------
// Flash-style attention (fp32, online softmax).
// grid: (SEQ/64, BATCH*HEADS), block 256.
// 64-query tile x 64-key tiles, D=64. Per thread: 4 query rows x 4 (key|dim)
// lanes, interleaved (L + 16*j) for conflict-free smem (stride 65).
// ---------------------------------------------------------------------------
#define SSTR 65
#define ATTN_SMEM (4 * 64 * SSTR * 4)

__global__ __launch_bounds__(256)
void attn_kernel(const float* __restrict__ qkv, float* __restrict__ out)
{
    extern __shared__ float sm[];
    float* Qs = sm;
    float* Ks = sm + 64 * SSTR;
    float* Vs = sm + 2 * 64 * SSTR;
    float* Ps = sm + 3 * 64 * SSTR;

    const int tid = threadIdx.x;
    const int L  = tid & 15;
    const int gq = tid >> 4;          // 16 groups; rows gq*4 .. gq*4+3
    const int qt = blockIdx.x;
    const int b  = blockIdx.y >> 4;
    const int h  = blockIdx.y & 15;

    const int lrow = tid >> 2;        // 0..63
    const int lcol = (tid & 3) << 4;  // 0,16,32,48

    // Load Q tile (64 x 64)
    {
        const float* qb = qkv + ((size_t)(b * SEQ + qt * 64 + lrow)) * (3 * EMB)
                              + h * HDIM + lcol;
        #pragma unroll
        for (int i = 0; i < 4; ++i) {
            const float4 v = *(const float4*)(qb + i * 4);
            const int c = lcol + i * 4;
            Qs[lrow * SSTR + c + 0] = v.x;
            Qs[lrow * SSTR + c + 1] = v.y;
            Qs[lrow * SSTR + c + 2] = v.z;
            Qs[lrow * SSTR + c + 3] = v.w;
        }
    }

    float m_r[4], l_r[4], acc[4][4];
    #pragma unroll
    for (int i = 0; i < 4; ++i) {
        m_r[i] = -1e30f; l_r[i] = 0.f;
        #pragma unroll
        for (int j = 0; j < 4; ++j) acc[i][j] = 0.f;
    }

    const float* kb = qkv + ((size_t)(b * SEQ + lrow)) * (3 * EMB)
                          + EMB + h * HDIM + lcol;
    const float* vb = kb + EMB;

    for (int kt = 0; kt < SEQ / 64; ++kt) {
        const float* kp = kb + (size_t)kt * 64 * (3 * EMB);
        const float* vp = vb + (size_t)kt * 64 * (3 * EMB);
        #pragma unroll
        for (int i = 0; i < 4; ++i) {
            const float4 kv4 = *(const float4*)(kp + i * 4);
            const float4 vv4 = *(const float4*)(vp + i * 4);
            const int c = lcol + i * 4;
            Ks[lrow * SSTR + c + 0] = kv4.x; Ks[lrow * SSTR + c + 1] = kv4.y;
            Ks[lrow * SSTR + c + 2] = kv4.z; Ks[lrow * SSTR + c + 3] = kv4.w;
            Vs[lrow * SSTR + c + 0] = vv4.x; Vs[lrow * SSTR + c + 1] = vv4.y;
            Vs[lrow * SSTR + c + 2] = vv4.z; Vs[lrow * SSTR + c + 3] = vv4.w;
        }
        __syncthreads();

        // scores: s[i][j] = Q[gq*4+i] . K[L+16*j]
        float s[4][4];
        #pragma unroll
        for (int i = 0; i < 4; ++i)
            #pragma unroll
            for (int j = 0; j < 4; ++j) s[i][j] = 0.f;

        #pragma unroll 8
        for (int kd = 0; kd < 64; ++kd) {
            float rq[4];
            #pragma unroll
            for (int i = 0; i < 4; ++i) rq[i] = Qs[(gq * 4 + i) * SSTR + kd];
            #pragma unroll
            for (int j = 0; j < 4; ++j) {
                const float kk = Ks[(L + 16 * j) * SSTR + kd];
                #pragma unroll
                for (int i = 0; i < 4; ++i) s[i][j] = fmaf(rq[i], kk, s[i][j]);
            }
        }

        // online softmax update (per query row; stats replicated over 16 lanes)
        #pragma unroll
        for (int i = 0; i < 4; ++i) {
            float tm = -1e30f;
            #pragma unroll
            for (int j = 0; j < 4; ++j) { s[i][j] *= 0.125f; tm = fmaxf(tm, s[i][j]); }
            #pragma unroll
            for (int o = 8; o; o >>= 1) tm = fmaxf(tm, __shfl_xor_sync(0xffffffffu, tm, o));
            const float mnew = fmaxf(m_r[i], tm);
            const float alpha = __expf(m_r[i] - mnew);
            float psum = 0.f;
            #pragma unroll
            for (int j = 0; j < 4; ++j) {
                const float p = __expf(s[i][j] - mnew);
                s[i][j] = p; psum += p;
            }
            #pragma unroll
            for (int o = 8; o; o >>= 1) psum += __shfl_xor_sync(0xffffffffu, psum, o);
            l_r[i] = l_r[i] * alpha + psum;
            m_r[i] = mnew;
            #pragma unroll
            for (int j = 0; j < 4; ++j) acc[i][j] *= alpha;
            #pragma unroll
            for (int j = 0; j < 4; ++j) Ps[(gq * 4 + i) * SSTR + L + 16 * j] = s[i][j];
        }
        __syncthreads();

        // O += P @ V
        #pragma unroll 8
        for (int k = 0; k < 64; ++k) {
            float vv[4];
            #pragma unroll
            for (int j = 0; j < 4; ++j) vv[j] = Vs[k * SSTR + L + 16 * j];
            #pragma unroll
            for (int i = 0; i < 4; ++i) {
                const float p = Ps[(gq * 4 + i) * SSTR + k];
                #pragma unroll
                for (int j = 0; j < 4; ++j) acc[i][j] = fmaf(p, vv[j], acc[i][j]);
            }
        }
        __syncthreads();
    }

    // normalize + write: out[(b,q), h*64 + (L+16j)]
    #pragma unroll
    for (int i = 0; i < 4; ++i) {
        const float inv = 1.0f / l_r[i];
        const int r = b * SEQ + qt * 64 + gq * 4 + i;
        #pragma unroll
        for (int j = 0; j < 4; ++j)
            out[(size_t)r * EMB + h * HDIM + L + 16 * j] = acc[i][j] * inv;
    }
}

// ---------------------------------------------------------------------------
// Launch
// ---------------------------------------------------------------------------
extern "C" void kernel_launch(void* const* d_in, const int* in_sizes, int n_in,
                              void* d_out, int out_size)
{
    (void)in_sizes; (void)n_in; (void)out_size;
    const float* x     = (const float*)d_in[0];
    const float* qkv_w = (const float*)d_in[1];
    const float* qkv_b = (const float*)d_in[2];
    const float* out_w = (const float*)d_in[3];
    const float* out_b = (const float*)d_in[4];
    const float* ff1_w = (const float*)d_in[5];
    const float* ff1_b = (const float*)d_in[6];
    const float* ff2_w = (const float*)d_in[7];
    const float* ff2_b = (const float*)d_in[8];
    const float* ln1_g = (const float*)d_in[9];
    const float* ln1_b = (const float*)d_in[10];
    const float* ln2_g = (const float*)d_in[11];
    const float* ln2_b = (const float*)d_in[12];
    float* out = (float*)d_out;

    float *bh, *bqkv, *battn, *bx1, *bff1;
    cudaGetSymbolAddress((void**)&bh,    d_buf_h);
    cudaGetSymbolAddress((void**)&bqkv,  d_buf_qkv);
    cudaGetSymbolAddress((void**)&battn, d_buf_attn);
    cudaGetSymbolAddress((void**)&bx1,   d_buf_x1);
    cudaGetSymbolAddress((void**)&bff1,  d_buf_ff1);

    cudaFuncSetAttribute(attn_kernel,
                         cudaFuncAttributeMaxDynamicSharedMemorySize, ATTN_SMEM);

    // 1. LN1
    ln_kernel<<<NTOK, 256>>>(x, ln1_g, ln1_b, bh);
    // 2. QKV projection: [4096,1024] @ [3072,1024]^T
    sgemm_kernel<<<dim3(3 * EMB / 128, NTOK / 128), 256>>>(
        bh, qkv_w, qkv_b, nullptr, bqkv, NTOK, 3 * EMB, EMB, 0);
    // 3. Attention
    attn_kernel<<<dim3(SEQ / 64, BATCH * HEADS), 256, ATTN_SMEM>>>(bqkv, battn);
    // 4. Output projection + residual(x)
    sgemm_kernel<<<dim3(EMB / 128, NTOK / 128), 256>>>(
        battn, out_w, out_b, x, bx1, NTOK, EMB, EMB, 2);
    // 5. LN2
    ln_kernel<<<NTOK, 256>>>(bx1, ln2_g, ln2_b, bh);
    // 6. FF1 + GELU: [4096,1024] @ [4096,1024]^T
    sgemm_kernel<<<dim3(FFDIM / 128, NTOK / 128), 256>>>(
        bh, ff1_w, ff1_b, nullptr, bff1, NTOK, FFDIM, EMB, 1);
    // 7. FF2 + residual(x1) -> d_out
    sgemm_kernel<<<dim3(EMB / 128, NTOK / 128), 256>>>(
        bff1, ff2_w, ff2_b, bx1, out, NTOK, EMB, FFDIM, 2);
}

// round 6
// speedup vs baseline: 1.7474x; 1.7458x over previous
#include <cuda_runtime.h>
#include <cuda_bf16.h>
#include <math.h>
#include <stdint.h>

// Problem constants
#define BATCH 2
#define SEQ   2048
#define NTOK  4096
#define EMB   1024
#define HEADS 16
#define HDIM  64
#define FFDIM 4096

// ---------------------------------------------------------------------------
// Scratch buffers
// ---------------------------------------------------------------------------
__device__ float d_buf_h   [(size_t)NTOK * EMB];
__device__ float d_buf_qkv [(size_t)NTOK * 3 * EMB];
__device__ float d_buf_attn[(size_t)NTOK * EMB];
__device__ float d_buf_x1  [(size_t)NTOK * EMB];
__device__ float d_buf_ff1 [(size_t)NTOK * FFDIM];

// ---------------------------------------------------------------------------
// Helpers
// ---------------------------------------------------------------------------
__device__ __forceinline__ uint32_t smem_u32(const void* p) {
    uint32_t a;
    asm("{ .reg .u64 t; cvta.to.shared.u64 t, %1; cvt.u32.u64 %0, t; }"
        : "=r"(a) : "l"(p));
    return a;
}
__device__ __forceinline__ void cp_async16(uint32_t saddr, const void* gptr) {
    asm volatile("cp.async.cg.shared.global [%0], [%1], 16;"
                 :: "r"(saddr), "l"(gptr));
}
#define CP_COMMIT() asm volatile("cp.async.commit_group;" ::: "memory")
#define CP_WAIT(n)  asm volatile("cp.async.wait_group %0;" :: "n"(n) : "memory")

__device__ __forceinline__ void mma_tf32(float& c0, float& c1, float& c2, float& c3,
                                         uint32_t a0, uint32_t a1, uint32_t a2, uint32_t a3,
                                         uint32_t b0, uint32_t b1)
{
    asm volatile(
        "mma.sync.aligned.m16n8k8.row.col.f32.tf32.tf32.f32 "
        "{%0,%1,%2,%3}, {%4,%5,%6,%7}, {%8,%9}, {%0,%1,%2,%3};"
        : "+f"(c0), "+f"(c1), "+f"(c2), "+f"(c3)
        : "r"(a0), "r"(a1), "r"(a2), "r"(a3), "r"(b0), "r"(b1));
}

__device__ __forceinline__ float gelu_exact(float v)
{
    return 0.5f * v * (1.0f + erff(v * 0.70710678118654752f));
}

// ---------------------------------------------------------------------------
// LayerNorm
// ---------------------------------------------------------------------------
__global__ __launch_bounds__(256)
void ln_kernel(const float* __restrict__ x, const float* __restrict__ gamma,
               const float* __restrict__ beta, float* __restrict__ y)
{
    const int row = blockIdx.x;
    const int t = threadIdx.x;
    const float4 v = ((const float4*)(x + (size_t)row * EMB))[t];
    __shared__ float sh[8];

    float s = v.x + v.y + v.z + v.w;
    #pragma unroll
    for (int o = 16; o; o >>= 1) s += __shfl_xor_sync(0xffffffffu, s, o);
    if ((t & 31) == 0) sh[t >> 5] = s;
    __syncthreads();
    float tot = 0.f;
    #pragma unroll
    for (int w = 0; w < 8; ++w) tot += sh[w];
    const float mu = tot * (1.0f / (float)EMB);

    const float dx0 = v.x - mu, dx1 = v.y - mu, dx2 = v.z - mu, dx3 = v.w - mu;
    float q = dx0*dx0 + dx1*dx1 + dx2*dx2 + dx3*dx3;
    __syncthreads();
    #pragma unroll
    for (int o = 16; o; o >>= 1) q += __shfl_xor_sync(0xffffffffu, q, o);
    if ((t & 31) == 0) sh[t >> 5] = q;
    __syncthreads();
    float tq = 0.f;
    #pragma unroll
    for (int w = 0; w < 8; ++w) tq += sh[w];
    const float rstd = rsqrtf(tq * (1.0f / (float)EMB) + 1e-5f);

    const float4 g4 = ((const float4*)gamma)[t];
    const float4 b4 = ((const float4*)beta)[t];
    float4 o4;
    o4.x = dx0 * rstd * g4.x + b4.x;
    o4.y = dx1 * rstd * g4.y + b4.y;
    o4.z = dx2 * rstd * g4.z + b4.z;
    o4.w = dx3 * rstd * g4.w + b4.w;
    ((float4*)(y + (size_t)row * EMB))[t] = o4;
}

// ---------------------------------------------------------------------------
// tf32 mma.sync GEMM: C[M,N] = A[M,K] @ W[N,K]^T + bias (+ epilogue)
// 128x128 CTA tile, BK=16, 3-stage cp.async pipeline.
// 8 warps, warp tile 64x32 (2 row-warps x 4 col-warps), m16n8k8 fragments.
// modes: 0 = bias ; 1 = bias+GELU ; 2 = bias+residual
// ---------------------------------------------------------------------------
#define GBK     16
#define GSTR    20                   // padded row stride (floats)
#define OPW     (128 * GSTR)         // words per operand per stage
#define STW     (2 * OPW)            // words per stage (A + B)
#define GSTAGES 3
#define GEMM_SMEM (GSTAGES * STW * 4)

__global__ __launch_bounds__(256, 2)
void tf32_gemm_kernel(const float* __restrict__ A, const float* __restrict__ W,
                      const float* __restrict__ bias, const float* __restrict__ res,
                      float* __restrict__ C, int M, int N, int K, int mode)
{
    extern __shared__ float smf[];
    const uint32_t sb = smem_u32(smf);
    const int tid = threadIdx.x;
    const int wid = tid >> 5;
    const int lane = tid & 31;
    const int gid = lane >> 2;        // groupID (0..7)
    const int tig = lane & 3;         // thread-in-group (0..3)
    const int wrow = wid >> 2;        // 0..1
    const int wcol = wid & 3;         // 0..3
    const int row0 = blockIdx.y << 7;
    const int col0 = blockIdx.x << 7;
    const int nChunks = K >> 4;

    // cp.async geometry: thread covers rows (tid>>2) and (tid>>2)+64, c16 = tid&3
    const int ldr = tid >> 2;         // 0..63
    const int ldc = tid & 3;          // 16B column (0..3)
    const float* aSrc0 = A + (size_t)(row0 + ldr) * K + ldc * 4;
    const float* aSrc1 = A + (size_t)(row0 + ldr + 64) * K + ldc * 4;
    const float* wSrc0 = W + (size_t)(col0 + ldr) * K + ldc * 4;
    const float* wSrc1 = W + (size_t)(col0 + ldr + 64) * K + ldc * 4;
    const uint32_t dA0 = (ldr * GSTR + ldc * 4) * 4;
    const uint32_t dA1 = ((ldr + 64) * GSTR + ldc * 4) * 4;

    float acc[4][4][4];
    #pragma unroll
    for (int mt = 0; mt < 4; ++mt)
        #pragma unroll
        for (int nt = 0; nt < 4; ++nt)
            #pragma unroll
            for (int r = 0; r < 4; ++r) acc[mt][nt][r] = 0.f;

    // Prologue: issue chunks 0,1
    #pragma unroll
    for (int s = 0; s < 2; ++s) {
        const uint32_t stA = sb + s * STW * 4;
        const uint32_t stB = stA + OPW * 4;
        const int k0 = s * GBK;
        cp_async16(stA + dA0, aSrc0 + k0);
        cp_async16(stA + dA1, aSrc1 + k0);
        cp_async16(stB + dA0, wSrc0 + k0);
        cp_async16(stB + dA1, wSrc1 + k0);
        CP_COMMIT();
    }

    // Fragment smem base indices (word offsets within a stage)
    const int aBaseRow = wrow * 64;   // + mt*16 + gid (+8)
    const int bBaseRow = wcol * 32;   // + nt*8 + gid

    for (int i = 0; i < nChunks; ++i) {
        // issue chunk i+2
        const int j = i + 2;
        if (j < nChunks) {
            const int s = j % GSTAGES;
            const uint32_t stA = sb + s * STW * 4;
            const uint32_t stB = stA + OPW * 4;
            const int k0 = j * GBK;
            cp_async16(stA + dA0, aSrc0 + k0);
            cp_async16(stA + dA1, aSrc1 + k0);
            cp_async16(stB + dA0, wSrc0 + k0);
            cp_async16(stB + dA1, wSrc1 + k0);
        }
        CP_COMMIT();
        CP_WAIT(2);                    // chunk i resident
        __syncthreads();

        const float* As = smf + (i % GSTAGES) * STW;
        const float* Bs = As + OPW;

        #pragma unroll
        for (int ks = 0; ks < 16; ks += 8) {
            uint32_t af[4][4], bf[4][2];
            #pragma unroll
            for (int mt = 0; mt < 4; ++mt) {
                const int r = aBaseRow + mt * 16 + gid;
                af[mt][0] = __float_as_uint(As[(r    ) * GSTR + ks + tig    ]);
                af[mt][1] = __float_as_uint(As[(r + 8) * GSTR + ks + tig    ]);
                af[mt][2] = __float_as_uint(As[(r    ) * GSTR + ks + tig + 4]);
                af[mt][3] = __float_as_uint(As[(r + 8) * GSTR + ks + tig + 4]);
            }
            #pragma unroll
            for (int nt = 0; nt < 4; ++nt) {
                const int r = bBaseRow + nt * 8 + gid;
                bf[nt][0] = __float_as_uint(Bs[r * GSTR + ks + tig    ]);
                bf[nt][1] = __float_as_uint(Bs[r * GSTR + ks + tig + 4]);
            }
            #pragma unroll
            for (int mt = 0; mt < 4; ++mt)
                #pragma unroll
                for (int nt = 0; nt < 4; ++nt)
                    mma_tf32(acc[mt][nt][0], acc[mt][nt][1],
                             acc[mt][nt][2], acc[mt][nt][3],
                             af[mt][0], af[mt][1], af[mt][2], af[mt][3],
                             bf[nt][0], bf[nt][1]);
        }
        __syncthreads();
    }

    // Epilogue: c0,c1 at (row=gid, col=2*tig, 2*tig+1); c2,c3 at row=gid+8
    #pragma unroll
    for (int mt = 0; mt < 4; ++mt) {
        #pragma unroll
        for (int half = 0; half < 2; ++half) {
            const int r = row0 + wrow * 64 + mt * 16 + gid + half * 8;
            float* Crow = C + (size_t)r * N;
            const float* Rrow = res + (size_t)r * N;
            #pragma unroll
            for (int nt = 0; nt < 4; ++nt) {
                const int c = col0 + wcol * 32 + nt * 8 + 2 * tig;
                float o0 = acc[mt][nt][half * 2 + 0] + bias[c];
                float o1 = acc[mt][nt][half * 2 + 1] + bias[c + 1];
                if (mode == 1) {
                    o0 = gelu_exact(o0); o1 = gelu_exact(o1);
                } else if (mode == 2) {
                    const float2 rv = *(const float2*)(Rrow + c);
                    o0 += rv.x; o1 += rv.y;
                }
                float2 ov; ov.x = o0; ov.y = o1;
                *(float2*)(Crow + c) = ov;
            }
        }
    }
}

// ---------------------------------------------------------------------------
// Flash-style attention (fp32 SIMT, unchanged)
// ---------------------------------------------------------------------------
#define SSTR 65
#define ATTN_SMEM (4 * 64 * SSTR * 4)

__global__ __launch_bounds__(256)
void attn_kernel(const float* __restrict__ qkv, float* __restrict__ out)
{
    extern __shared__ float sm[];
    float* Qs = sm;
    float* Ks = sm + 64 * SSTR;
    float* Vs = sm + 2 * 64 * SSTR;
    float* Ps = sm + 3 * 64 * SSTR;

    const int tid = threadIdx.x;
    const int L  = tid & 15;
    const int gq = tid >> 4;
    const int qt = blockIdx.x;
    const int b  = blockIdx.y >> 4;
    const int h  = blockIdx.y & 15;

    const int lrow = tid >> 2;
    const int lcol = (tid & 3) << 4;

    {
        const float* qb = qkv + ((size_t)(b * SEQ + qt * 64 + lrow)) * (3 * EMB)
                              + h * HDIM + lcol;
        #pragma unroll
        for (int i = 0; i < 4; ++i) {
            const float4 v = *(const float4*)(qb + i * 4);
            const int c = lcol + i * 4;
            Qs[lrow * SSTR + c + 0] = v.x;
            Qs[lrow * SSTR + c + 1] = v.y;
            Qs[lrow * SSTR + c + 2] = v.z;
            Qs[lrow * SSTR + c + 3] = v.w;
        }
    }

    float m_r[4], l_r[4], acc[4][4];
    #pragma unroll
    for (int i = 0; i < 4; ++i) {
        m_r[i] = -1e30f; l_r[i] = 0.f;
        #pragma unroll
        for (int j = 0; j < 4; ++j) acc[i][j] = 0.f;
    }

    const float* kb = qkv + ((size_t)(b * SEQ + lrow)) * (3 * EMB)
                          + EMB + h * HDIM + lcol;
    const float* vb = kb + EMB;

    for (int kt = 0; kt < SEQ / 64; ++kt) {
        const float* kp = kb + (size_t)kt * 64 * (3 * EMB);
        const float* vp = vb + (size_t)kt * 64 * (3 * EMB);
        #pragma unroll
        for (int i = 0; i < 4; ++i) {
            const float4 kv4 = *(const float4*)(kp + i * 4);
            const float4 vv4 = *(const float4*)(vp + i * 4);
            const int c = lcol + i * 4;
            Ks[lrow * SSTR + c + 0] = kv4.x; Ks[lrow * SSTR + c + 1] = kv4.y;
            Ks[lrow * SSTR + c + 2] = kv4.z; Ks[lrow * SSTR + c + 3] = kv4.w;
            Vs[lrow * SSTR + c + 0] = vv4.x; Vs[lrow * SSTR + c + 1] = vv4.y;
            Vs[lrow * SSTR + c + 2] = vv4.z; Vs[lrow * SSTR + c + 3] = vv4.w;
        }
        __syncthreads();

        float s[4][4];
        #pragma unroll
        for (int i = 0; i < 4; ++i)
            #pragma unroll
            for (int j = 0; j < 4; ++j) s[i][j] = 0.f;

        #pragma unroll 8
        for (int kd = 0; kd < 64; ++kd) {
            float rq[4];
            #pragma unroll
            for (int i = 0; i < 4; ++i) rq[i] = Qs[(gq * 4 + i) * SSTR + kd];
            #pragma unroll
            for (int j = 0; j < 4; ++j) {
                const float kk = Ks[(L + 16 * j) * SSTR + kd];
                #pragma unroll
                for (int i = 0; i < 4; ++i) s[i][j] = fmaf(rq[i], kk, s[i][j]);
            }
        }

        #pragma unroll
        for (int i = 0; i < 4; ++i) {
            float tm = -1e30f;
            #pragma unroll
            for (int j = 0; j < 4; ++j) { s[i][j] *= 0.125f; tm = fmaxf(tm, s[i][j]); }
            #pragma unroll
            for (int o = 8; o; o >>= 1) tm = fmaxf(tm, __shfl_xor_sync(0xffffffffu, tm, o));
            const float mnew = fmaxf(m_r[i], tm);
            const float alpha = __expf(m_r[i] - mnew);
            float psum = 0.f;
            #pragma unroll
            for (int j = 0; j < 4; ++j) {
                const float p = __expf(s[i][j] - mnew);
                s[i][j] = p; psum += p;
            }
            #pragma unroll
            for (int o = 8; o; o >>= 1) psum += __shfl_xor_sync(0xffffffffu, psum, o);
            l_r[i] = l_r[i] * alpha + psum;
            m_r[i] = mnew;
            #pragma unroll
            for (int j = 0; j < 4; ++j) acc[i][j] *= alpha;
            #pragma unroll
            for (int j = 0; j < 4; ++j) Ps[(gq * 4 + i) * SSTR + L + 16 * j] = s[i][j];
        }
        __syncthreads();

        #pragma unroll 8
        for (int k = 0; k < 64; ++k) {
            float vv[4];
            #pragma unroll
            for (int j = 0; j < 4; ++j) vv[j] = Vs[k * SSTR + L + 16 * j];
            #pragma unroll
            for (int i = 0; i < 4; ++i) {
                const float p = Ps[(gq * 4 + i) * SSTR + k];
                #pragma unroll
                for (int j = 0; j < 4; ++j) acc[i][j] = fmaf(p, vv[j], acc[i][j]);
            }
        }
        __syncthreads();
    }

    #pragma unroll
    for (int i = 0; i < 4; ++i) {
        const float inv = 1.0f / l_r[i];
        const int r = b * SEQ + qt * 64 + gq * 4 + i;
        #pragma unroll
        for (int j = 0; j < 4; ++j)
            out[(size_t)r * EMB + h * HDIM + L + 16 * j] = acc[i][j] * inv;
    }
}

// ---------------------------------------------------------------------------
// Launch
// ---------------------------------------------------------------------------
extern "C" void kernel_launch(void* const* d_in, const int* in_sizes, int n_in,
                              void* d_out, int out_size)
{
    (void)in_sizes; (void)n_in; (void)out_size;
    const float* x     = (const float*)d_in[0];
    const float* qkv_w = (const float*)d_in[1];
    const float* qkv_b = (const float*)d_in[2];
    const float* out_w = (const float*)d_in[3];
    const float* out_b = (const float*)d_in[4];
    const float* ff1_w = (const float*)d_in[5];
    const float* ff1_b = (const float*)d_in[6];
    const float* ff2_w = (const float*)d_in[7];
    const float* ff2_b = (const float*)d_in[8];
    const float* ln1_g = (const float*)d_in[9];
    const float* ln1_b = (const float*)d_in[10];
    const float* ln2_g = (const float*)d_in[11];
    const float* ln2_b = (const float*)d_in[12];
    float* out = (float*)d_out;

    float *bh, *bqkv, *battn, *bx1, *bff1;
    cudaGetSymbolAddress((void**)&bh,    d_buf_h);
    cudaGetSymbolAddress((void**)&bqkv,  d_buf_qkv);
    cudaGetSymbolAddress((void**)&battn, d_buf_attn);
    cudaGetSymbolAddress((void**)&bx1,   d_buf_x1);
    cudaGetSymbolAddress((void**)&bff1,  d_buf_ff1);

    cudaFuncSetAttribute(attn_kernel,
                         cudaFuncAttributeMaxDynamicSharedMemorySize, ATTN_SMEM);
    cudaFuncSetAttribute(tf32_gemm_kernel,
                         cudaFuncAttributeMaxDynamicSharedMemorySize, GEMM_SMEM);

    // 1. LN1
    ln_kernel<<<NTOK, 256>>>(x, ln1_g, ln1_b, bh);
    // 2. QKV projection
    tf32_gemm_kernel<<<dim3(3 * EMB / 128, NTOK / 128), 256, GEMM_SMEM>>>(
        bh, qkv_w, qkv_b, nullptr, bqkv, NTOK, 3 * EMB, EMB, 0);
    // 3. Attention
    attn_kernel<<<dim3(SEQ / 64, BATCH * HEADS), 256, ATTN_SMEM>>>(bqkv, battn);
    // 4. Output projection + residual(x)
    tf32_gemm_kernel<<<dim3(EMB / 128, NTOK / 128), 256, GEMM_SMEM>>>(
        battn, out_w, out_b, x, bx1, NTOK, EMB, EMB, 2);
    // 5. LN2
    ln_kernel<<<NTOK, 256>>>(bx1, ln2_g, ln2_b, bh);
    // 6. FF1 + GELU
    tf32_gemm_kernel<<<dim3(FFDIM / 128, NTOK / 128), 256, GEMM_SMEM>>>(
        bh, ff1_w, ff1_b, nullptr, bff1, NTOK, FFDIM, EMB, 1);
    // 7. FF2 + residual(x1)
    tf32_gemm_kernel<<<dim3(EMB / 128, NTOK / 128), 256, GEMM_SMEM>>>(
        bff1, ff2_w, ff2_b, bx1, out, NTOK, EMB, FFDIM, 2);
}

// round 9
// speedup vs baseline: 2.7319x; 1.5634x over previous
#include <cuda_runtime.h>
#include <cuda_bf16.h>
#include <math.h>
#include <stdint.h>

// Problem constants
#define BATCH 2
#define SEQ   2048
#define NTOK  4096
#define EMB   1024
#define HEADS 16
#define HDIM  64
#define FFDIM 4096

// ---------------------------------------------------------------------------
// Scratch buffers
// ---------------------------------------------------------------------------
__device__ float d_buf_h   [(size_t)NTOK * EMB];
__device__ float d_buf_qkv [(size_t)NTOK * 3 * EMB];
__device__ float d_buf_attn[(size_t)NTOK * EMB];
__device__ float d_buf_x1  [(size_t)NTOK * EMB];
__device__ float d_buf_ff1 [(size_t)NTOK * FFDIM];

// ---------------------------------------------------------------------------
// Helpers
// ---------------------------------------------------------------------------
__device__ __forceinline__ uint32_t smem_u32(const void* p) {
    uint32_t a;
    asm("{ .reg .u64 t; cvta.to.shared.u64 t, %1; cvt.u32.u64 %0, t; }"
        : "=r"(a) : "l"(p));
    return a;
}
__device__ __forceinline__ void cp_async16(uint32_t saddr, const void* gptr) {
    asm volatile("cp.async.cg.shared.global [%0], [%1], 16;"
                 :: "r"(saddr), "l"(gptr));
}
#define CP_COMMIT() asm volatile("cp.async.commit_group;" ::: "memory")
#define CP_WAIT(n)  asm volatile("cp.async.wait_group %0;" :: "n"(n) : "memory")

__device__ __forceinline__ uint32_t rna_tf32(float f) {
    uint32_t r;
    asm("cvt.rna.tf32.f32 %0, %1;" : "=r"(r) : "f"(f));
    return r;
}
__device__ __forceinline__ float rna_tf32_f(float f) {
    return __uint_as_float(rna_tf32(f));
}

__device__ __forceinline__ void mma_tf32(float& c0, float& c1, float& c2, float& c3,
                                         uint32_t a0, uint32_t a1, uint32_t a2, uint32_t a3,
                                         uint32_t b0, uint32_t b1)
{
    asm volatile(
        "mma.sync.aligned.m16n8k8.row.col.f32.tf32.tf32.f32 "
        "{%0,%1,%2,%3}, {%4,%5,%6,%7}, {%8,%9}, {%0,%1,%2,%3};"
        : "+f"(c0), "+f"(c1), "+f"(c2), "+f"(c3)
        : "r"(a0), "r"(a1), "r"(a2), "r"(a3), "r"(b0), "r"(b1));
}

__device__ __forceinline__ float gelu_exact(float v)
{
    return 0.5f * v * (1.0f + erff(v * 0.70710678118654752f));
}

// ---------------------------------------------------------------------------
// LayerNorm
// ---------------------------------------------------------------------------
__global__ __launch_bounds__(256)
void ln_kernel(const float* __restrict__ x, const float* __restrict__ gamma,
               const float* __restrict__ beta, float* __restrict__ y)
{
    const int row = blockIdx.x;
    const int t = threadIdx.x;
    const float4 v = ((const float4*)(x + (size_t)row * EMB))[t];
    __shared__ float sh[8];

    float s = v.x + v.y + v.z + v.w;
    #pragma unroll
    for (int o = 16; o; o >>= 1) s += __shfl_xor_sync(0xffffffffu, s, o);
    if ((t & 31) == 0) sh[t >> 5] = s;
    __syncthreads();
    float tot = 0.f;
    #pragma unroll
    for (int w = 0; w < 8; ++w) tot += sh[w];
    const float mu = tot * (1.0f / (float)EMB);

    const float dx0 = v.x - mu, dx1 = v.y - mu, dx2 = v.z - mu, dx3 = v.w - mu;
    float q = dx0*dx0 + dx1*dx1 + dx2*dx2 + dx3*dx3;
    __syncthreads();
    #pragma unroll
    for (int o = 16; o; o >>= 1) q += __shfl_xor_sync(0xffffffffu, q, o);
    if ((t & 31) == 0) sh[t >> 5] = q;
    __syncthreads();
    float tq = 0.f;
    #pragma unroll
    for (int w = 0; w < 8; ++w) tq += sh[w];
    const float rstd = rsqrtf(tq * (1.0f / (float)EMB) + 1e-5f);

    const float4 g4 = ((const float4*)gamma)[t];
    const float4 b4 = ((const float4*)beta)[t];
    float4 o4;
    o4.x = dx0 * rstd * g4.x + b4.x;
    o4.y = dx1 * rstd * g4.y + b4.y;
    o4.z = dx2 * rstd * g4.z + b4.z;
    o4.w = dx3 * rstd * g4.w + b4.w;
    ((float4*)(y + (size_t)row * EMB))[t] = o4;
}

// ---------------------------------------------------------------------------
// tf32 mma.sync GEMM + cvt.rna on fragments
// ---------------------------------------------------------------------------
#define GBK     16
#define GSTR    20
#define OPW     (128 * GSTR)
#define STW     (2 * OPW)
#define GSTAGES 3
#define GEMM_SMEM (GSTAGES * STW * 4)

__global__ __launch_bounds__(256, 2)
void tf32_gemm_kernel(const float* __restrict__ A, const float* __restrict__ W,
                      const float* __restrict__ bias, const float* __restrict__ res,
                      float* __restrict__ C, int M, int N, int K, int mode)
{
    extern __shared__ float smf[];
    const uint32_t sb = smem_u32(smf);
    const int tid = threadIdx.x;
    const int wid = tid >> 5;
    const int lane = tid & 31;
    const int gid = lane >> 2;
    const int tig = lane & 3;
    const int wrow = wid >> 2;
    const int wcol = wid & 3;
    const int row0 = blockIdx.y << 7;
    const int col0 = blockIdx.x << 7;
    const int nChunks = K >> 4;

    const int ldr = tid >> 2;
    const int ldc = tid & 3;
    const float* aSrc0 = A + (size_t)(row0 + ldr) * K + ldc * 4;
    const float* aSrc1 = A + (size_t)(row0 + ldr + 64) * K + ldc * 4;
    const float* wSrc0 = W + (size_t)(col0 + ldr) * K + ldc * 4;
    const float* wSrc1 = W + (size_t)(col0 + ldr + 64) * K + ldc * 4;
    const uint32_t dA0 = (ldr * GSTR + ldc * 4) * 4;
    const uint32_t dA1 = ((ldr + 64) * GSTR + ldc * 4) * 4;

    float acc[4][4][4];
    #pragma unroll
    for (int mt = 0; mt < 4; ++mt)
        #pragma unroll
        for (int nt = 0; nt < 4; ++nt)
            #pragma unroll
            for (int r = 0; r < 4; ++r) acc[mt][nt][r] = 0.f;

    #pragma unroll
    for (int s = 0; s < 2; ++s) {
        const uint32_t stA = sb + s * STW * 4;
        const uint32_t stB = stA + OPW * 4;
        const int k0 = s * GBK;
        cp_async16(stA + dA0, aSrc0 + k0);
        cp_async16(stA + dA1, aSrc1 + k0);
        cp_async16(stB + dA0, wSrc0 + k0);
        cp_async16(stB + dA1, wSrc1 + k0);
        CP_COMMIT();
    }

    const int aBaseRow = wrow * 64;
    const int bBaseRow = wcol * 32;

    for (int i = 0; i < nChunks; ++i) {
        const int j = i + 2;
        if (j < nChunks) {
            const int s = j % GSTAGES;
            const uint32_t stA = sb + s * STW * 4;
            const uint32_t stB = stA + OPW * 4;
            const int k0 = j * GBK;
            cp_async16(stA + dA0, aSrc0 + k0);
            cp_async16(stA + dA1, aSrc1 + k0);
            cp_async16(stB + dA0, wSrc0 + k0);
            cp_async16(stB + dA1, wSrc1 + k0);
        }
        CP_COMMIT();
        CP_WAIT(2);
        __syncthreads();

        const float* As = smf + (i % GSTAGES) * STW;
        const float* Bs = As + OPW;

        #pragma unroll
        for (int ks = 0; ks < 16; ks += 8) {
            uint32_t af[4][4], bf[4][2];
            #pragma unroll
            for (int mt = 0; mt < 4; ++mt) {
                const int r = aBaseRow + mt * 16 + gid;
                af[mt][0] = rna_tf32(As[(r    ) * GSTR + ks + tig    ]);
                af[mt][1] = rna_tf32(As[(r + 8) * GSTR + ks + tig    ]);
                af[mt][2] = rna_tf32(As[(r    ) * GSTR + ks + tig + 4]);
                af[mt][3] = rna_tf32(As[(r + 8) * GSTR + ks + tig + 4]);
            }
            #pragma unroll
            for (int nt = 0; nt < 4; ++nt) {
                const int r = bBaseRow + nt * 8 + gid;
                bf[nt][0] = rna_tf32(Bs[r * GSTR + ks + tig    ]);
                bf[nt][1] = rna_tf32(Bs[r * GSTR + ks + tig + 4]);
            }
            #pragma unroll
            for (int mt = 0; mt < 4; ++mt)
                #pragma unroll
                for (int nt = 0; nt < 4; ++nt)
                    mma_tf32(acc[mt][nt][0], acc[mt][nt][1],
                             acc[mt][nt][2], acc[mt][nt][3],
                             af[mt][0], af[mt][1], af[mt][2], af[mt][3],
                             bf[nt][0], bf[nt][1]);
        }
        __syncthreads();
    }

    #pragma unroll
    for (int mt = 0; mt < 4; ++mt) {
        #pragma unroll
        for (int half = 0; half < 2; ++half) {
            const int r = row0 + wrow * 64 + mt * 16 + gid + half * 8;
            float* Crow = C + (size_t)r * N;
            const float* Rrow = res + (size_t)r * N;
            #pragma unroll
            for (int nt = 0; nt < 4; ++nt) {
                const int c = col0 + wcol * 32 + nt * 8 + 2 * tig;
                float o0 = acc[mt][nt][half * 2 + 0] + bias[c];
                float o1 = acc[mt][nt][half * 2 + 1] + bias[c + 1];
                if (mode == 1) {
                    o0 = gelu_exact(o0); o1 = gelu_exact(o1);
                } else if (mode == 2) {
                    const float2 rv = *(const float2*)(Rrow + c);
                    o0 += rv.x; o1 += rv.y;
                }
                float2 ov; ov.x = o0; ov.y = o1;
                *(float2*)(Crow + c) = ov;
            }
        }
    }
}

// ---------------------------------------------------------------------------
// Flash attention with tf32 mma.sync.
// CTA: 128 queries x one (batch, head); 8 warps, 16 q-rows per warp.
// Key tile: 64. smem: Qs(->Ps overlay) [128x68], Ks [64x68], Vt [64x68] (V^T).
// ---------------------------------------------------------------------------
#define ASTR 68
#define A_QP 0
#define A_KS (128 * ASTR)
#define A_VT (A_KS + 64 * ASTR)
#define ATTN_SMEM ((128 * ASTR + 64 * ASTR + 64 * ASTR) * 4)

__global__ __launch_bounds__(256, 2)
void attn_mma_kernel(const float* __restrict__ qkv, float* __restrict__ out)
{
    extern __shared__ float sm[];
    float* Qs = sm + A_QP;          // later reused as Ps
    float* Ps = sm + A_QP;
    float* Ks = sm + A_KS;
    float* Vt = sm + A_VT;
    const uint32_t sb = smem_u32(sm);

    const int tid  = threadIdx.x;
    const int wid  = tid >> 5;
    const int lane = tid & 31;
    const int gid  = lane >> 2;
    const int tig  = lane & 3;
    const int qt   = blockIdx.x;
    const int b    = blockIdx.y >> 4;
    const int h    = blockIdx.y & 15;

    const int ldr = tid >> 2;        // 0..63 (row within tile)
    const int ldc = tid & 3;         // 16-float column segment (0..3)

    // ---- Load Q tile (128 x 64): full 64-col coverage ----
    {
        const float* q0 = qkv + ((size_t)(b * SEQ + qt * 128 + ldr)) * (3 * EMB)
                              + h * HDIM + ldc * 16;
        const float* q1 = q0 + (size_t)64 * (3 * EMB);
        #pragma unroll
        for (int jj = 0; jj < 4; ++jj) {
            cp_async16(sb + (A_QP + ldr * ASTR + ldc * 16 + jj * 4) * 4,
                       q0 + jj * 4);
            cp_async16(sb + (A_QP + (ldr + 64) * ASTR + ldc * 16 + jj * 4) * 4,
                       q1 + jj * 4);
        }
        CP_COMMIT();
        CP_WAIT(0);
    }
    __syncthreads();

    uint32_t qa[8][4];
    {
        const int r0 = wid * 16 + gid;
        #pragma unroll
        for (int ks = 0; ks < 8; ++ks) {
            qa[ks][0] = rna_tf32(Qs[(r0    ) * ASTR + ks * 8 + tig    ]);
            qa[ks][1] = rna_tf32(Qs[(r0 + 8) * ASTR + ks * 8 + tig    ]);
            qa[ks][2] = rna_tf32(Qs[(r0    ) * ASTR + ks * 8 + tig + 4]);
            qa[ks][3] = rna_tf32(Qs[(r0 + 8) * ASTR + ks * 8 + tig + 4]);
        }
    }

    float m_r[2] = {-1e30f, -1e30f};
    float l_r[2] = {0.f, 0.f};
    float oacc[8][4];
    #pragma unroll
    for (int nt = 0; nt < 8; ++nt)
        #pragma unroll
        for (int r = 0; r < 4; ++r) oacc[nt][r] = 0.f;

    const float* kBase = qkv + ((size_t)(b * SEQ + ldr)) * (3 * EMB)
                             + EMB + h * HDIM;
    const float* vBase = kBase + EMB;

    for (int kt = 0; kt < SEQ / 64; ++kt) {
        __syncthreads();   // Ks/Vt/Ps free (prev tile fully consumed)

        // K tile (64 x 64) via cp.async: full coverage
        {
            const float* kg = kBase + (size_t)kt * 64 * (3 * EMB) + ldc * 16;
            #pragma unroll
            for (int jj = 0; jj < 4; ++jj)
                cp_async16(sb + (A_KS + ldr * ASTR + ldc * 16 + jj * 4) * 4,
                           kg + jj * 4);
        }
        // V tile: load rows, store transposed (round-to-nearest tf32)
        const float* vg = vBase + (size_t)kt * 64 * (3 * EMB);
        float4 vv[4];
        #pragma unroll
        for (int jj = 0; jj < 4; ++jj)
            vv[jj] = *(const float4*)(vg + ldc * 16 + jj * 4);
        CP_COMMIT();
        CP_WAIT(0);
        #pragma unroll
        for (int jj = 0; jj < 4; ++jj) {
            const int d0 = ldc * 16 + jj * 4;
            Vt[(d0 + 0) * ASTR + ldr] = rna_tf32_f(vv[jj].x);
            Vt[(d0 + 1) * ASTR + ldr] = rna_tf32_f(vv[jj].y);
            Vt[(d0 + 2) * ASTR + ldr] = rna_tf32_f(vv[jj].z);
            Vt[(d0 + 3) * ASTR + ldr] = rna_tf32_f(vv[jj].w);
        }
        __syncthreads();

        // ---- S = Q @ K^T  (warp: 16q x 64k) ----
        float sacc[8][4];
        #pragma unroll
        for (int nt = 0; nt < 8; ++nt)
            #pragma unroll
            for (int r = 0; r < 4; ++r) sacc[nt][r] = 0.f;

        #pragma unroll
        for (int ks = 0; ks < 8; ++ks) {
            #pragma unroll
            for (int nt = 0; nt < 8; ++nt) {
                const int kr = nt * 8 + gid;
                const uint32_t b0 = rna_tf32(Ks[kr * ASTR + ks * 8 + tig    ]);
                const uint32_t b1 = rna_tf32(Ks[kr * ASTR + ks * 8 + tig + 4]);
                mma_tf32(sacc[nt][0], sacc[nt][1], sacc[nt][2], sacc[nt][3],
                         qa[ks][0], qa[ks][1], qa[ks][2], qa[ks][3], b0, b1);
            }
        }

        // ---- online softmax on fragments ----
        const int prow = wid * 16 + gid;
        #pragma unroll
        for (int hr = 0; hr < 2; ++hr) {
            float tm = -1e30f;
            #pragma unroll
            for (int nt = 0; nt < 8; ++nt) {
                sacc[nt][hr*2+0] *= 0.125f;
                sacc[nt][hr*2+1] *= 0.125f;
                tm = fmaxf(tm, fmaxf(sacc[nt][hr*2+0], sacc[nt][hr*2+1]));
            }
            tm = fmaxf(tm, __shfl_xor_sync(0xffffffffu, tm, 1));
            tm = fmaxf(tm, __shfl_xor_sync(0xffffffffu, tm, 2));
            const float mnew = fmaxf(m_r[hr], tm);
            const float alpha = __expf(m_r[hr] - mnew);
            float psum = 0.f;
            #pragma unroll
            for (int nt = 0; nt < 8; ++nt) {
                const float p0 = __expf(sacc[nt][hr*2+0] - mnew);
                const float p1 = __expf(sacc[nt][hr*2+1] - mnew);
                psum += p0 + p1;
                float2 pv;
                pv.x = rna_tf32_f(p0);
                pv.y = rna_tf32_f(p1);
                *(float2*)&Ps[(prow + hr * 8) * ASTR + nt * 8 + 2 * tig] = pv;
                oacc[nt][hr*2+0] *= alpha;
                oacc[nt][hr*2+1] *= alpha;
            }
            psum += __shfl_xor_sync(0xffffffffu, psum, 1);
            psum += __shfl_xor_sync(0xffffffffu, psum, 2);
            l_r[hr] = l_r[hr] * alpha + psum;
            m_r[hr] = mnew;
        }
        __syncthreads();

        // ---- O += P @ V ----
        #pragma unroll
        for (int ks = 0; ks < 8; ++ks) {
            uint32_t pa[4];
            pa[0] = __float_as_uint(Ps[(prow    ) * ASTR + ks * 8 + tig    ]);
            pa[1] = __float_as_uint(Ps[(prow + 8) * ASTR + ks * 8 + tig    ]);
            pa[2] = __float_as_uint(Ps[(prow    ) * ASTR + ks * 8 + tig + 4]);
            pa[3] = __float_as_uint(Ps[(prow + 8) * ASTR + ks * 8 + tig + 4]);
            #pragma unroll
            for (int nt = 0; nt < 8; ++nt) {
                const int dr = nt * 8 + gid;
                const uint32_t b0 = __float_as_uint(Vt[dr * ASTR + ks * 8 + tig    ]);
                const uint32_t b1 = __float_as_uint(Vt[dr * ASTR + ks * 8 + tig + 4]);
                mma_tf32(oacc[nt][0], oacc[nt][1], oacc[nt][2], oacc[nt][3],
                         pa[0], pa[1], pa[2], pa[3], b0, b1);
            }
        }
    }

    // ---- epilogue ----
    #pragma unroll
    for (int hr = 0; hr < 2; ++hr) {
        const float inv = 1.0f / l_r[hr];
        const int token = b * SEQ + qt * 128 + wid * 16 + gid + hr * 8;
        float* orow = out + (size_t)token * EMB + h * HDIM;
        #pragma unroll
        for (int nt = 0; nt < 8; ++nt) {
            float2 ov;
            ov.x = oacc[nt][hr*2+0] * inv;
            ov.y = oacc[nt][hr*2+1] * inv;
            *(float2*)(orow + nt * 8 + 2 * tig) = ov;
        }
    }
}

// ---------------------------------------------------------------------------
// Launch
// ---------------------------------------------------------------------------
extern "C" void kernel_launch(void* const* d_in, const int* in_sizes, int n_in,
                              void* d_out, int out_size)
{
    (void)in_sizes; (void)n_in; (void)out_size;
    const float* x     = (const float*)d_in[0];
    const float* qkv_w = (const float*)d_in[1];
    const float* qkv_b = (const float*)d_in[2];
    const float* out_w = (const float*)d_in[3];
    const float* out_b = (const float*)d_in[4];
    const float* ff1_w = (const float*)d_in[5];
    const float* ff1_b = (const float*)d_in[6];
    const float* ff2_w = (const float*)d_in[7];
    const float* ff2_b = (const float*)d_in[8];
    const float* ln1_g = (const float*)d_in[9];
    const float* ln1_b = (const float*)d_in[10];
    const float* ln2_g = (const float*)d_in[11];
    const float* ln2_b = (const float*)d_in[12];
    float* out = (float*)d_out;

    float *bh, *bqkv, *battn, *bx1, *bff1;
    cudaGetSymbolAddress((void**)&bh,    d_buf_h);
    cudaGetSymbolAddress((void**)&bqkv,  d_buf_qkv);
    cudaGetSymbolAddress((void**)&battn, d_buf_attn);
    cudaGetSymbolAddress((void**)&bx1,   d_buf_x1);
    cudaGetSymbolAddress((void**)&bff1,  d_buf_ff1);

    cudaFuncSetAttribute(attn_mma_kernel,
                         cudaFuncAttributeMaxDynamicSharedMemorySize, ATTN_SMEM);
    cudaFuncSetAttribute(tf32_gemm_kernel,
                         cudaFuncAttributeMaxDynamicSharedMemorySize, GEMM_SMEM);

    // 1. LN1
    ln_kernel<<<NTOK, 256>>>(x, ln1_g, ln1_b, bh);
    // 2. QKV projection
    tf32_gemm_kernel<<<dim3(3 * EMB / 128, NTOK / 128), 256, GEMM_SMEM>>>(
        bh, qkv_w, qkv_b, nullptr, bqkv, NTOK, 3 * EMB, EMB, 0);
    // 3. Attention (tensor-core flash)
    attn_mma_kernel<<<dim3(SEQ / 128, BATCH * HEADS), 256, ATTN_SMEM>>>(bqkv, battn);
    // 4. Output projection + residual(x)
    tf32_gemm_kernel<<<dim3(EMB / 128, NTOK / 128), 256, GEMM_SMEM>>>(
        battn, out_w, out_b, x, bx1, NTOK, EMB, EMB, 2);
    // 5. LN2
    ln_kernel<<<NTOK, 256>>>(bx1, ln2_g, ln2_b, bh);
    // 6. FF1 + GELU
    tf32_gemm_kernel<<<dim3(FFDIM / 128, NTOK / 128), 256, GEMM_SMEM>>>(
        bh, ff1_w, ff1_b, nullptr, bff1, NTOK, FFDIM, EMB, 1);
    // 7. FF2 + residual(x1)
    tf32_gemm_kernel<<<dim3(EMB / 128, NTOK / 128), 256, GEMM_SMEM>>>(
        bff1, ff2_w, ff2_b, bx1, out, NTOK, EMB, FFDIM, 2);
}